// round 14
// baseline (speedup 1.0000x reference)
#include <cuda_runtime.h>
#include <cuda_fp16.h>
#include <math.h>
#include <stdint.h>

typedef unsigned long long ull;

// Problem constants
constexpr int N_PTS   = 65536;
constexpr int KP      = 15;
constexpr int IN_F    = 64;
constexpr int OUT_F   = 128;
constexpr int RDIM    = KP * IN_F;          // 960
constexpr float INV_EXT = 1.0f / 0.024f;
constexpr float BN_EPS  = 1e-6f;
constexpr float NEG_SLOPE = 0.1f;

// Scratch
__device__ __half g_Ph[(size_t)N_PTS * RDIM];   // P fp16 (hi only)
__device__ __half g_Whh[(size_t)RDIM * OUT_F];  // W fp16 hi
__device__ __half g_Whl[(size_t)RDIM * OUT_F];  // W fp16 lo residual
__device__ float g_psum[512 * OUT_F];
__device__ float g_psq [512 * OUT_F];
__device__ float g_scale[OUT_F];
__device__ float g_bias [OUT_F];

__device__ __forceinline__ uint32_t smem_u32(const void* p) {
    uint32_t a;
    asm("{ .reg .u64 t; cvta.to.shared.u64 t, %1; cvt.u32.u64 %0, t; }" : "=r"(a) : "l"(p));
    return a;
}

// ---- mma.sync + cp.async helpers ----
__device__ __forceinline__ void ldmatrix_x4(uint32_t* r, uint32_t addr) {
    asm volatile("ldmatrix.sync.aligned.m8n8.x4.shared.b16 {%0,%1,%2,%3}, [%4];"
                 : "=r"(r[0]), "=r"(r[1]), "=r"(r[2]), "=r"(r[3]) : "r"(addr));
}
__device__ __forceinline__ void ldmatrix_x4_t(uint32_t* r, uint32_t addr) {
    asm volatile("ldmatrix.sync.aligned.m8n8.x4.trans.shared.b16 {%0,%1,%2,%3}, [%4];"
                 : "=r"(r[0]), "=r"(r[1]), "=r"(r[2]), "=r"(r[3]) : "r"(addr));
}
__device__ __forceinline__ void mma16816(float* c, const uint32_t* a,
                                         const uint32_t* b) {
    asm volatile(
        "mma.sync.aligned.m16n8k16.row.col.f32.f16.f16.f32 "
        "{%0,%1,%2,%3}, {%4,%5,%6,%7}, {%8,%9}, {%0,%1,%2,%3};"
        : "+f"(c[0]), "+f"(c[1]), "+f"(c[2]), "+f"(c[3])
        : "r"(a[0]), "r"(a[1]), "r"(a[2]), "r"(a[3]), "r"(b[0]), "r"(b[1]));
}
__device__ __forceinline__ void cp16(uint32_t saddr, const void* gptr) {
    asm volatile("cp.async.cg.shared.global [%0], [%1], 16;"
                 :: "r"(saddr), "l"(gptr) : "memory");
}
#define CP_COMMIT() asm volatile("cp.async.commit_group;" ::: "memory")
#define CP_WAIT(n)  asm volatile("cp.async.wait_group %0;" :: "n"(n) : "memory")

// =====================================================================
// K0: split W[k][o] -> fp16 hi/lo
// =====================================================================
__global__ __launch_bounds__(256) void k0_prep(const float* __restrict__ W) {
    const int idx = blockIdx.x * 256 + threadIdx.x;
    if (idx >= RDIM * OUT_F) return;
    const float w = W[idx];
    const __half hi = __float2half_rn(w);
    g_Whh[idx] = hi;
    g_Whl[idx] = __float2half_rn(w - __half2float(hi));
}

// =====================================================================
// K1 v3: per-point mma.  P[16,64] = w[16,32] @ f[32,64], one warp/point.
// w and f both hi/lo split -> 3-term mma (numerically ~exact to fp32).
// 4 warps/CTA, 46KB static smem, 4 CTAs/SM.
// =====================================================================
constexpr int FS = 72;   // f smem stride (halfs): 144B rows, conflict-free trans
constexpr int WS = 40;   // w smem stride (halfs): 80B rows, conflict-free

__global__ __launch_bounds__(128, 4) void k1_weighted(
    const float* __restrict__ qp, const float* __restrict__ sp,
    const int*   __restrict__ nbr, const float* __restrict__ feat,
    const float* __restrict__ kpts)
{
    __shared__ __half fh_s[4][32 * FS];
    __shared__ __half fl_s[4][32 * FS];
    __shared__ __half wh_s[4][16 * WS];
    __shared__ __half wl_s[4][16 * WS];
    __shared__ float  kp_s[KP][3];

    const int t = threadIdx.x;
    const int warp = t >> 5, lane = t & 31;
    const int gpt = blockIdx.x * 4 + warp;

    if (t < 45) ((float*)kp_s)[t] = kpts[t];
    __syncthreads();

    // --- weights: lane owns neighbor column `lane` ---
    const int j = __ldg(nbr + (size_t)gpt * 32 + lane);
    const float qx = __ldg(qp + gpt * 3 + 0);
    const float qy = __ldg(qp + gpt * 3 + 1);
    const float qz = __ldg(qp + gpt * 3 + 2);
    const float dx = __ldg(sp + (size_t)j * 3 + 0) - qx;
    const float dy = __ldg(sp + (size_t)j * 3 + 1) - qy;
    const float dz = __ldg(sp + (size_t)j * 3 + 2) - qz;

    #pragma unroll
    for (int k = 0; k < KP; k++) {
        const float ax = dx - kp_s[k][0];
        const float ay = dy - kp_s[k][1];
        const float az = dz - kp_s[k][2];
        const float sq = ax * ax + ay * ay + az * az;
        const float w = fmaxf(1.0f - sqrtf(sq) * INV_EXT, 0.0f);
        const __half wh = __float2half_rn(w);
        wh_s[warp][k * WS + lane] = wh;
        wl_s[warp][k * WS + lane] = __float2half_rn(w - __half2float(wh));
    }
    wh_s[warp][15 * WS + lane] = __ushort_as_half(0);
    wl_s[warp][15 * WS + lane] = __ushort_as_half(0);

    // --- features: row m = neighbor, cols = 64 features, hi/lo split ---
    #pragma unroll 4
    for (int m = 0; m < 32; m++) {
        const int jj = __shfl_sync(0xffffffffu, j, m);
        const float2 f = __ldg(reinterpret_cast<const float2*>(
            feat + (size_t)jj * IN_F) + lane);
        const __half2 fh = __floats2half2_rn(f.x, f.y);
        const float2 fhf = __half22float2(fh);
        const __half2 fl = __floats2half2_rn(f.x - fhf.x, f.y - fhf.y);
        *reinterpret_cast<__half2*>(&fh_s[warp][m * FS + 2 * lane]) = fh;
        *reinterpret_cast<__half2*>(&fl_s[warp][m * FS + 2 * lane]) = fl;
    }
    __syncwarp();

    // --- A fragments (w), 2 k-steps x (hi, lo) ---
    const uint32_t aWh = smem_u32(wh_s[warp]);
    const uint32_t aWl = smem_u32(wl_s[warp]);
    uint32_t Awh[2][4], Awl[2][4];
    #pragma unroll
    for (int ks = 0; ks < 2; ks++) {
        const uint32_t off =
            (uint32_t)((lane & 15) * WS + ks * 16 + ((lane >> 4) << 3)) * 2;
        ldmatrix_x4(Awh[ks], aWh + off);
        ldmatrix_x4(Awl[ks], aWl + off);
    }

    // --- mma: 2 ksteps x 4 col-groups x 3 terms ---
    const uint32_t aFh = smem_u32(fh_s[warp]);
    const uint32_t aFl = smem_u32(fl_s[warp]);
    float acc[8][4];
    #pragma unroll
    for (int n = 0; n < 8; n++)
        #pragma unroll
        for (int e = 0; e < 4; e++) acc[n][e] = 0.0f;

    #pragma unroll
    for (int ks = 0; ks < 2; ks++) {
        #pragma unroll
        for (int g = 0; g < 4; g++) {
            uint32_t Bh[4], Bl[4];
            const uint32_t off = (uint32_t)(
                (ks * 16 + (lane & 15)) * FS + g * 16 + ((lane >> 4) << 3)) * 2;
            ldmatrix_x4_t(Bh, aFh + off);
            ldmatrix_x4_t(Bl, aFl + off);
            mma16816(acc[2 * g],     Awh[ks], &Bh[0]);
            mma16816(acc[2 * g + 1], Awh[ks], &Bh[2]);
            mma16816(acc[2 * g],     Awh[ks], &Bl[0]);
            mma16816(acc[2 * g + 1], Awh[ks], &Bl[2]);
            mma16816(acc[2 * g],     Awl[ks], &Bh[0]);
            mma16816(acc[2 * g + 1], Awl[ks], &Bh[2]);
        }
    }

    // --- epilogue: store P rows 0-14 as fp16 ---
    const size_t pbase = (size_t)gpt * RDIM;
    const int r0 = lane >> 2;
    #pragma unroll
    for (int g = 0; g < 8; g++) {
        const int col = g * 8 + (lane & 3) * 2;
        *reinterpret_cast<__half2*>(g_Ph + pbase + r0 * IN_F + col) =
            __floats2half2_rn(acc[g][0], acc[g][1]);
        if (r0 != 7)
            *reinterpret_cast<__half2*>(g_Ph + pbase + (r0 + 8) * IN_F + col) =
                __floats2half2_rn(acc[g][2], acc[g][3]);
    }
}

// =====================================================================
// K2: cp.async double-buffered 2-term GEMM + fused BN partial stats
// =====================================================================
constexpr int SA = 40;
constexpr int SB = 136;
constexpr int AH_BYTES = 128 * SA * 2;        // 10240
constexpr int BH_BYTES = 32 * SB * 2;         // 8704
constexpr int OFF_BH   = AH_BYTES;
constexpr int OFF_BL   = AH_BYTES + BH_BYTES;
constexpr int STAGE_BYTES = AH_BYTES + 2 * BH_BYTES; // 27648
constexpr int K2_SMEM  = 2 * STAGE_BYTES;     // 55296

__device__ __forceinline__ void k2_load_chunk(
    uint32_t sbase, size_t rowBase, int k0, int tid)
{
    #pragma unroll
    for (int p = 0; p < 2; p++) {
        const int idx = p * 256 + tid;
        const int row = idx >> 2, c = idx & 3;
        const size_t go = (rowBase + row) * RDIM + k0 + c * 8;
        cp16(sbase + (uint32_t)(row * SA + c * 8) * 2, g_Ph + go);
        const int brow = idx >> 4, bc = idx & 15;
        const size_t gb = (size_t)(k0 + brow) * OUT_F + bc * 8;
        const uint32_t sb = (uint32_t)(brow * SB + bc * 8) * 2;
        cp16(sbase + OFF_BH + sb, g_Whh + gb);
        cp16(sbase + OFF_BL + sb, g_Whl + gb);
    }
    CP_COMMIT();
}

__global__ __launch_bounds__(256, 2) void k2_gemm_mma(float* __restrict__ out)
{
    extern __shared__ __align__(16) char smem[];
    const uint32_t s0 = smem_u32(smem);

    const int tid  = threadIdx.x;
    const int lane = tid & 31, warp = tid >> 5;
    const int warp_m = warp & 3;
    const int warp_n = warp >> 2;
    const size_t rowBase = (size_t)blockIdx.x * 128;

    float acc[2][8][4];
    #pragma unroll
    for (int mt = 0; mt < 2; mt++)
        #pragma unroll
        for (int nt = 0; nt < 8; nt++)
            #pragma unroll
            for (int e = 0; e < 4; e++) acc[mt][nt][e] = 0.0f;

    k2_load_chunk(s0, rowBase, 0, tid);

    for (int t = 0; t < RDIM / 32; t++) {
        if (t + 1 < RDIM / 32) {
            k2_load_chunk(s0 + ((t + 1) & 1) * STAGE_BYTES, rowBase,
                          (t + 1) * 32, tid);
            CP_WAIT(1);
        } else {
            CP_WAIT(0);
        }
        __syncthreads();

        const uint32_t stg = s0 + (t & 1) * STAGE_BYTES;
        const uint32_t aAh = stg;
        const uint32_t aBh = stg + OFF_BH, aBl = stg + OFF_BL;

        #pragma unroll
        for (int ks = 0; ks < 32; ks += 16) {
            uint32_t Afh[2][4];
            #pragma unroll
            for (int mt = 0; mt < 2; mt++) {
                const int r = warp_m * 32 + mt * 16 + (lane & 15);
                const int col = ks + ((lane >> 4) << 3);
                ldmatrix_x4(Afh[mt], aAh + (uint32_t)(r * SA + col) * 2);
            }
            #pragma unroll
            for (int g = 0; g < 4; g++) {
                uint32_t Bfh[4], Bfl[4];
                const int kr = ks + (lane & 15);
                const int nc = warp_n * 64 + g * 16 + ((lane >> 4) << 3);
                const uint32_t off = (uint32_t)(kr * SB + nc) * 2;
                ldmatrix_x4_t(Bfh, aBh + off);
                ldmatrix_x4_t(Bfl, aBl + off);
                #pragma unroll
                for (int mt = 0; mt < 2; mt++) {
                    mma16816(acc[mt][2 * g],     Afh[mt], &Bfh[0]);
                    mma16816(acc[mt][2 * g + 1], Afh[mt], &Bfh[2]);
                    mma16816(acc[mt][2 * g],     Afh[mt], &Bfl[0]);
                    mma16816(acc[mt][2 * g + 1], Afh[mt], &Bfl[2]);
                }
            }
        }
        __syncthreads();
    }

    // out stores
    #pragma unroll
    for (int mt = 0; mt < 2; mt++) {
        const int r0 = (int)rowBase + warp_m * 32 + mt * 16 + (lane >> 2);
        #pragma unroll
        for (int nt = 0; nt < 8; nt++) {
            const int c0 = warp_n * 64 + nt * 8 + (lane & 3) * 2;
            *reinterpret_cast<float2*>(out + (size_t)r0 * OUT_F + c0) =
                make_float2(acc[mt][nt][0], acc[mt][nt][1]);
            *reinterpret_cast<float2*>(out + (size_t)(r0 + 8) * OUT_F + c0) =
                make_float2(acc[mt][nt][2], acc[mt][nt][3]);
        }
    }

    // fused BN partial stats (deterministic): per-thread row sums -> shfl
    // across lane>>2 -> smem across warp_m -> g_psum/g_psq per CTA.
    float s2[16], q2[16];
    #pragma unroll
    for (int nt = 0; nt < 8; nt++)
        #pragma unroll
        for (int e = 0; e < 2; e++) {
            const float a0 = acc[0][nt][e],     a1 = acc[0][nt][e + 2];
            const float a2 = acc[1][nt][e],     a3 = acc[1][nt][e + 2];
            s2[nt * 2 + e] = a0 + a1 + a2 + a3;
            q2[nt * 2 + e] = a0 * a0 + a1 * a1 + a2 * a2 + a3 * a3;
        }
    #pragma unroll
    for (int d = 16; d >= 4; d >>= 1)
        #pragma unroll
        for (int i = 0; i < 16; i++) {
            s2[i] += __shfl_xor_sync(0xffffffffu, s2[i], d);
            q2[i] += __shfl_xor_sync(0xffffffffu, q2[i], d);
        }

    float* s_part = reinterpret_cast<float*>(smem);        // [8][64]
    float* q_part = s_part + 512;                          // [8][64]
    if (lane < 4) {
        #pragma unroll
        for (int i = 0; i < 16; i++) {
            const int cl = (i >> 1) * 8 + lane * 2 + (i & 1);
            s_part[warp * 64 + cl] = s2[i];
            q_part[warp * 64 + cl] = q2[i];
        }
    }
    __syncthreads();
    if (tid < 128) {
        const int c = tid, cl = c & 63, wn = c >> 6;
        float ssum = 0.0f, qsum = 0.0f;
        #pragma unroll
        for (int wm = 0; wm < 4; wm++) {
            ssum += s_part[(wn * 4 + wm) * 64 + cl];
            qsum += q_part[(wn * 4 + wm) * 64 + cl];
        }
        g_psum[blockIdx.x * OUT_F + c] = ssum;
        g_psq [blockIdx.x * OUT_F + c] = qsum;
    }
}

// =====================================================================
// K3b: finalize over 512 CTA partials (one CTA per column)
// =====================================================================
__global__ __launch_bounds__(256) void k3b_finalize(const float* __restrict__ gamma,
                                                    const float* __restrict__ beta)
{
    __shared__ float ss[256], qq[256];
    const int c = blockIdx.x;
    const int t = threadIdx.x;
    ss[t] = g_psum[t * OUT_F + c] + g_psum[(t + 256) * OUT_F + c];
    qq[t] = g_psq [t * OUT_F + c] + g_psq [(t + 256) * OUT_F + c];
    __syncthreads();
    #pragma unroll
    for (int stp = 128; stp > 0; stp >>= 1) {
        if (t < stp) { ss[t] += ss[t + stp]; qq[t] += qq[t + stp]; }
        __syncthreads();
    }
    if (t == 0) {
        const float inv_n = 1.0f / (float)N_PTS;
        const float mean = ss[0] * inv_n;
        const float var  = qq[0] * inv_n - mean * mean;
        const float sc   = gamma[c] * rsqrtf(var + BN_EPS);
        g_scale[c] = sc;
        g_bias[c]  = beta[c] - mean * sc;
    }
}

// K4: in-place BN affine + LeakyReLU
__global__ __launch_bounds__(256) void k4_bnrelu(float* __restrict__ x)
{
    const int i = blockIdx.x * 256 + threadIdx.x;
    float4 v = reinterpret_cast<float4*>(x)[i];
    const int c0 = (i * 4) & 127;
    const float4 sc = *reinterpret_cast<const float4*>(g_scale + c0);
    const float4 bi = *reinterpret_cast<const float4*>(g_bias + c0);
    v.x = fmaf(v.x, sc.x, bi.x); v.x = (v.x >= 0.0f) ? v.x : NEG_SLOPE * v.x;
    v.y = fmaf(v.y, sc.y, bi.y); v.y = (v.y >= 0.0f) ? v.y : NEG_SLOPE * v.y;
    v.z = fmaf(v.z, sc.z, bi.z); v.z = (v.z >= 0.0f) ? v.z : NEG_SLOPE * v.z;
    v.w = fmaf(v.w, sc.w, bi.w); v.w = (v.w >= 0.0f) ? v.w : NEG_SLOPE * v.w;
    reinterpret_cast<float4*>(x)[i] = v;
}

// =====================================================================
extern "C" void kernel_launch(void* const* d_in, const int* in_sizes, int n_in,
                              void* d_out, int out_size)
{
    const float* qp    = (const float*)d_in[0];
    const float* sp    = (const float*)d_in[1];
    const int*   nbr   = (const int*)  d_in[2];
    const float* feat  = (const float*)d_in[3];
    const float* kpts  = (const float*)d_in[4];
    const float* Wf    = (const float*)d_in[5];
    const float* gamma = (const float*)d_in[6];
    const float* beta  = (const float*)d_in[7];
    float* out = (float*)d_out;

    cudaFuncSetAttribute(k2_gemm_mma,
                         cudaFuncAttributeMaxDynamicSharedMemorySize, K2_SMEM);

    k0_prep<<<(RDIM * OUT_F + 255) / 256, 256>>>(Wf);
    k1_weighted<<<N_PTS / 4, 128>>>(qp, sp, nbr, feat, kpts);
    k2_gemm_mma<<<N_PTS / 128, 256, K2_SMEM>>>(out);
    k3b_finalize<<<OUT_F, 256>>>(gamma, beta);
    k4_bnrelu<<<(N_PTS * OUT_F / 4) / 256, 256>>>(out);
}

// round 15
// speedup vs baseline: 1.0063x; 1.0063x over previous
#include <cuda_runtime.h>
#include <cuda_fp16.h>
#include <math.h>
#include <stdint.h>

typedef unsigned long long ull;

// Problem constants
constexpr int N_PTS   = 65536;
constexpr int KP      = 15;
constexpr int IN_F    = 64;
constexpr int OUT_F   = 128;
constexpr int RDIM    = KP * IN_F;          // 960
constexpr float INV_EXT = 1.0f / 0.024f;
constexpr float BN_EPS  = 1e-6f;
constexpr float NEG_SLOPE = 0.1f;

// Scratch
__device__ __half g_Ph[(size_t)N_PTS * RDIM];   // P fp16 (hi only)
__device__ __half g_Whh[(size_t)RDIM * OUT_F];  // W fp16 hi
__device__ __half g_Whl[(size_t)RDIM * OUT_F];  // W fp16 lo residual
__device__ float g_psum[512 * OUT_F];
__device__ float g_psq [512 * OUT_F];
__device__ float g_scale[OUT_F];
__device__ float g_bias [OUT_F];

__device__ __forceinline__ uint32_t smem_u32(const void* p) {
    uint32_t a;
    asm("{ .reg .u64 t; cvta.to.shared.u64 t, %1; cvt.u32.u64 %0, t; }" : "=r"(a) : "l"(p));
    return a;
}

// ---- mma.sync + cp.async helpers ----
__device__ __forceinline__ void ldmatrix_x4(uint32_t* r, uint32_t addr) {
    asm volatile("ldmatrix.sync.aligned.m8n8.x4.shared.b16 {%0,%1,%2,%3}, [%4];"
                 : "=r"(r[0]), "=r"(r[1]), "=r"(r[2]), "=r"(r[3]) : "r"(addr));
}
__device__ __forceinline__ void ldmatrix_x4_t(uint32_t* r, uint32_t addr) {
    asm volatile("ldmatrix.sync.aligned.m8n8.x4.trans.shared.b16 {%0,%1,%2,%3}, [%4];"
                 : "=r"(r[0]), "=r"(r[1]), "=r"(r[2]), "=r"(r[3]) : "r"(addr));
}
__device__ __forceinline__ void mma16816(float* c, const uint32_t* a,
                                         const uint32_t* b) {
    asm volatile(
        "mma.sync.aligned.m16n8k16.row.col.f32.f16.f16.f32 "
        "{%0,%1,%2,%3}, {%4,%5,%6,%7}, {%8,%9}, {%0,%1,%2,%3};"
        : "+f"(c[0]), "+f"(c[1]), "+f"(c[2]), "+f"(c[3])
        : "r"(a[0]), "r"(a[1]), "r"(a[2]), "r"(a[3]), "r"(b[0]), "r"(b[1]));
}
__device__ __forceinline__ void cp16(uint32_t saddr, const void* gptr) {
    asm volatile("cp.async.cg.shared.global [%0], [%1], 16;"
                 :: "r"(saddr), "l"(gptr) : "memory");
}
#define CP_COMMIT() asm volatile("cp.async.commit_group;" ::: "memory")
#define CP_WAIT(n)  asm volatile("cp.async.wait_group %0;" :: "n"(n) : "memory")

// =====================================================================
// K0: split W[k][o] -> fp16 hi/lo
// =====================================================================
__global__ __launch_bounds__(256) void k0_prep(const float* __restrict__ W) {
    const int idx = blockIdx.x * 256 + threadIdx.x;
    if (idx >= RDIM * OUT_F) return;
    const float w = W[idx];
    const __half hi = __float2half_rn(w);
    g_Whh[idx] = hi;
    g_Whl[idx] = __float2half_rn(w - __half2float(hi));
}

// =====================================================================
// K1 v3: per-point mma.  P[16,64] = w[16,32] @ f[32,64], one warp/point.
// w and f both hi/lo split -> 3-term mma (numerically ~exact to fp32).
// 4 warps/CTA, 46KB static smem, 4 CTAs/SM.
// =====================================================================
constexpr int FS = 72;   // f smem stride (halfs): 144B rows, conflict-free trans
constexpr int WS = 40;   // w smem stride (halfs): 80B rows, conflict-free

__global__ __launch_bounds__(128, 4) void k1_weighted(
    const float* __restrict__ qp, const float* __restrict__ sp,
    const int*   __restrict__ nbr, const float* __restrict__ feat,
    const float* __restrict__ kpts)
{
    __shared__ __half fh_s[4][32 * FS];
    __shared__ __half fl_s[4][32 * FS];
    __shared__ __half wh_s[4][16 * WS];
    __shared__ __half wl_s[4][16 * WS];
    __shared__ float  kp_s[KP][3];

    const int t = threadIdx.x;
    const int warp = t >> 5, lane = t & 31;
    const int gpt = blockIdx.x * 4 + warp;

    if (t < 45) ((float*)kp_s)[t] = kpts[t];
    __syncthreads();

    // --- weights: lane owns neighbor column `lane` ---
    const int j = __ldg(nbr + (size_t)gpt * 32 + lane);
    const float qx = __ldg(qp + gpt * 3 + 0);
    const float qy = __ldg(qp + gpt * 3 + 1);
    const float qz = __ldg(qp + gpt * 3 + 2);
    const float dx = __ldg(sp + (size_t)j * 3 + 0) - qx;
    const float dy = __ldg(sp + (size_t)j * 3 + 1) - qy;
    const float dz = __ldg(sp + (size_t)j * 3 + 2) - qz;

    #pragma unroll
    for (int k = 0; k < KP; k++) {
        const float ax = dx - kp_s[k][0];
        const float ay = dy - kp_s[k][1];
        const float az = dz - kp_s[k][2];
        const float sq = ax * ax + ay * ay + az * az;
        const float w = fmaxf(1.0f - sqrtf(sq) * INV_EXT, 0.0f);
        const __half wh = __float2half_rn(w);
        wh_s[warp][k * WS + lane] = wh;
        wl_s[warp][k * WS + lane] = __float2half_rn(w - __half2float(wh));
    }
    wh_s[warp][15 * WS + lane] = __ushort_as_half(0);
    wl_s[warp][15 * WS + lane] = __ushort_as_half(0);

    // --- features: row m = neighbor, cols = 64 features, hi/lo split ---
    #pragma unroll 4
    for (int m = 0; m < 32; m++) {
        const int jj = __shfl_sync(0xffffffffu, j, m);
        const float2 f = __ldg(reinterpret_cast<const float2*>(
            feat + (size_t)jj * IN_F) + lane);
        const __half2 fh = __floats2half2_rn(f.x, f.y);
        const float2 fhf = __half22float2(fh);
        const __half2 fl = __floats2half2_rn(f.x - fhf.x, f.y - fhf.y);
        *reinterpret_cast<__half2*>(&fh_s[warp][m * FS + 2 * lane]) = fh;
        *reinterpret_cast<__half2*>(&fl_s[warp][m * FS + 2 * lane]) = fl;
    }
    __syncwarp();

    // --- A fragments (w), 2 k-steps x (hi, lo) ---
    const uint32_t aWh = smem_u32(wh_s[warp]);
    const uint32_t aWl = smem_u32(wl_s[warp]);
    uint32_t Awh[2][4], Awl[2][4];
    #pragma unroll
    for (int ks = 0; ks < 2; ks++) {
        const uint32_t off =
            (uint32_t)((lane & 15) * WS + ks * 16 + ((lane >> 4) << 3)) * 2;
        ldmatrix_x4(Awh[ks], aWh + off);
        ldmatrix_x4(Awl[ks], aWl + off);
    }

    // --- mma: 2 ksteps x 4 col-groups x 3 terms ---
    const uint32_t aFh = smem_u32(fh_s[warp]);
    const uint32_t aFl = smem_u32(fl_s[warp]);
    float acc[8][4];
    #pragma unroll
    for (int n = 0; n < 8; n++)
        #pragma unroll
        for (int e = 0; e < 4; e++) acc[n][e] = 0.0f;

    #pragma unroll
    for (int ks = 0; ks < 2; ks++) {
        #pragma unroll
        for (int g = 0; g < 4; g++) {
            uint32_t Bh[4], Bl[4];
            const uint32_t off = (uint32_t)(
                (ks * 16 + (lane & 15)) * FS + g * 16 + ((lane >> 4) << 3)) * 2;
            ldmatrix_x4_t(Bh, aFh + off);
            ldmatrix_x4_t(Bl, aFl + off);
            mma16816(acc[2 * g],     Awh[ks], &Bh[0]);
            mma16816(acc[2 * g + 1], Awh[ks], &Bh[2]);
            mma16816(acc[2 * g],     Awh[ks], &Bl[0]);
            mma16816(acc[2 * g + 1], Awh[ks], &Bl[2]);
            mma16816(acc[2 * g],     Awl[ks], &Bh[0]);
            mma16816(acc[2 * g + 1], Awl[ks], &Bh[2]);
        }
    }

    // --- epilogue: store P rows 0-14 as fp16 ---
    const size_t pbase = (size_t)gpt * RDIM;
    const int r0 = lane >> 2;
    #pragma unroll
    for (int g = 0; g < 8; g++) {
        const int col = g * 8 + (lane & 3) * 2;
        *reinterpret_cast<__half2*>(g_Ph + pbase + r0 * IN_F + col) =
            __floats2half2_rn(acc[g][0], acc[g][1]);
        if (r0 != 7)
            *reinterpret_cast<__half2*>(g_Ph + pbase + (r0 + 8) * IN_F + col) =
                __floats2half2_rn(acc[g][2], acc[g][3]);
    }
}

// =====================================================================
// K2: cp.async double-buffered 2-term GEMM + fused BN partial stats
// =====================================================================
constexpr int SA = 40;
constexpr int SB = 136;
constexpr int AH_BYTES = 128 * SA * 2;        // 10240
constexpr int BH_BYTES = 32 * SB * 2;         // 8704
constexpr int OFF_BH   = AH_BYTES;
constexpr int OFF_BL   = AH_BYTES + BH_BYTES;
constexpr int STAGE_BYTES = AH_BYTES + 2 * BH_BYTES; // 27648
constexpr int K2_SMEM  = 2 * STAGE_BYTES;     // 55296

__device__ __forceinline__ void k2_load_chunk(
    uint32_t sbase, size_t rowBase, int k0, int tid)
{
    #pragma unroll
    for (int p = 0; p < 2; p++) {
        const int idx = p * 256 + tid;
        const int row = idx >> 2, c = idx & 3;
        const size_t go = (rowBase + row) * RDIM + k0 + c * 8;
        cp16(sbase + (uint32_t)(row * SA + c * 8) * 2, g_Ph + go);
        const int brow = idx >> 4, bc = idx & 15;
        const size_t gb = (size_t)(k0 + brow) * OUT_F + bc * 8;
        const uint32_t sb = (uint32_t)(brow * SB + bc * 8) * 2;
        cp16(sbase + OFF_BH + sb, g_Whh + gb);
        cp16(sbase + OFF_BL + sb, g_Whl + gb);
    }
    CP_COMMIT();
}

__global__ __launch_bounds__(256, 2) void k2_gemm_mma(float* __restrict__ out)
{
    extern __shared__ __align__(16) char smem[];
    const uint32_t s0 = smem_u32(smem);

    const int tid  = threadIdx.x;
    const int lane = tid & 31, warp = tid >> 5;
    const int warp_m = warp & 3;
    const int warp_n = warp >> 2;
    const size_t rowBase = (size_t)blockIdx.x * 128;

    float acc[2][8][4];
    #pragma unroll
    for (int mt = 0; mt < 2; mt++)
        #pragma unroll
        for (int nt = 0; nt < 8; nt++)
            #pragma unroll
            for (int e = 0; e < 4; e++) acc[mt][nt][e] = 0.0f;

    k2_load_chunk(s0, rowBase, 0, tid);

    for (int t = 0; t < RDIM / 32; t++) {
        if (t + 1 < RDIM / 32) {
            k2_load_chunk(s0 + ((t + 1) & 1) * STAGE_BYTES, rowBase,
                          (t + 1) * 32, tid);
            CP_WAIT(1);
        } else {
            CP_WAIT(0);
        }
        __syncthreads();

        const uint32_t stg = s0 + (t & 1) * STAGE_BYTES;
        const uint32_t aAh = stg;
        const uint32_t aBh = stg + OFF_BH, aBl = stg + OFF_BL;

        #pragma unroll
        for (int ks = 0; ks < 32; ks += 16) {
            uint32_t Afh[2][4];
            #pragma unroll
            for (int mt = 0; mt < 2; mt++) {
                const int r = warp_m * 32 + mt * 16 + (lane & 15);
                const int col = ks + ((lane >> 4) << 3);
                ldmatrix_x4(Afh[mt], aAh + (uint32_t)(r * SA + col) * 2);
            }
            #pragma unroll
            for (int g = 0; g < 4; g++) {
                uint32_t Bfh[4], Bfl[4];
                const int kr = ks + (lane & 15);
                const int nc = warp_n * 64 + g * 16 + ((lane >> 4) << 3);
                const uint32_t off = (uint32_t)(kr * SB + nc) * 2;
                ldmatrix_x4_t(Bfh, aBh + off);
                ldmatrix_x4_t(Bfl, aBl + off);
                #pragma unroll
                for (int mt = 0; mt < 2; mt++) {
                    mma16816(acc[mt][2 * g],     Afh[mt], &Bfh[0]);
                    mma16816(acc[mt][2 * g + 1], Afh[mt], &Bfh[2]);
                    mma16816(acc[mt][2 * g],     Afh[mt], &Bfl[0]);
                    mma16816(acc[mt][2 * g + 1], Afh[mt], &Bfl[2]);
                }
            }
        }
        __syncthreads();
    }

    // out stores
    #pragma unroll
    for (int mt = 0; mt < 2; mt++) {
        const int r0 = (int)rowBase + warp_m * 32 + mt * 16 + (lane >> 2);
        #pragma unroll
        for (int nt = 0; nt < 8; nt++) {
            const int c0 = warp_n * 64 + nt * 8 + (lane & 3) * 2;
            *reinterpret_cast<float2*>(out + (size_t)r0 * OUT_F + c0) =
                make_float2(acc[mt][nt][0], acc[mt][nt][1]);
            *reinterpret_cast<float2*>(out + (size_t)(r0 + 8) * OUT_F + c0) =
                make_float2(acc[mt][nt][2], acc[mt][nt][3]);
        }
    }

    // fused BN partial stats (deterministic): per-thread row sums -> shfl
    // across lane>>2 -> smem across warp_m -> g_psum/g_psq per CTA.
    float s2[16], q2[16];
    #pragma unroll
    for (int nt = 0; nt < 8; nt++)
        #pragma unroll
        for (int e = 0; e < 2; e++) {
            const float a0 = acc[0][nt][e],     a1 = acc[0][nt][e + 2];
            const float a2 = acc[1][nt][e],     a3 = acc[1][nt][e + 2];
            s2[nt * 2 + e] = a0 + a1 + a2 + a3;
            q2[nt * 2 + e] = a0 * a0 + a1 * a1 + a2 * a2 + a3 * a3;
        }
    #pragma unroll
    for (int d = 16; d >= 4; d >>= 1)
        #pragma unroll
        for (int i = 0; i < 16; i++) {
            s2[i] += __shfl_xor_sync(0xffffffffu, s2[i], d);
            q2[i] += __shfl_xor_sync(0xffffffffu, q2[i], d);
        }

    float* s_part = reinterpret_cast<float*>(smem);        // [8][64]
    float* q_part = s_part + 512;                          // [8][64]
    if (lane < 4) {
        #pragma unroll
        for (int i = 0; i < 16; i++) {
            const int cl = (i >> 1) * 8 + lane * 2 + (i & 1);
            s_part[warp * 64 + cl] = s2[i];
            q_part[warp * 64 + cl] = q2[i];
        }
    }
    __syncthreads();
    if (tid < 128) {
        const int c = tid, cl = c & 63, wn = c >> 6;
        float ssum = 0.0f, qsum = 0.0f;
        #pragma unroll
        for (int wm = 0; wm < 4; wm++) {
            ssum += s_part[(wn * 4 + wm) * 64 + cl];
            qsum += q_part[(wn * 4 + wm) * 64 + cl];
        }
        g_psum[blockIdx.x * OUT_F + c] = ssum;
        g_psq [blockIdx.x * OUT_F + c] = qsum;
    }
}

// =====================================================================
// K3b: finalize over 512 CTA partials (one CTA per column)
// =====================================================================
__global__ __launch_bounds__(256) void k3b_finalize(const float* __restrict__ gamma,
                                                    const float* __restrict__ beta)
{
    __shared__ float ss[256], qq[256];
    const int c = blockIdx.x;
    const int t = threadIdx.x;
    ss[t] = g_psum[t * OUT_F + c] + g_psum[(t + 256) * OUT_F + c];
    qq[t] = g_psq [t * OUT_F + c] + g_psq [(t + 256) * OUT_F + c];
    __syncthreads();
    #pragma unroll
    for (int stp = 128; stp > 0; stp >>= 1) {
        if (t < stp) { ss[t] += ss[t + stp]; qq[t] += qq[t + stp]; }
        __syncthreads();
    }
    if (t == 0) {
        const float inv_n = 1.0f / (float)N_PTS;
        const float mean = ss[0] * inv_n;
        const float var  = qq[0] * inv_n - mean * mean;
        const float sc   = gamma[c] * rsqrtf(var + BN_EPS);
        g_scale[c] = sc;
        g_bias[c]  = beta[c] - mean * sc;
    }
}

// K4: in-place BN affine + LeakyReLU
__global__ __launch_bounds__(256) void k4_bnrelu(float* __restrict__ x)
{
    const int i = blockIdx.x * 256 + threadIdx.x;
    float4 v = reinterpret_cast<float4*>(x)[i];
    const int c0 = (i * 4) & 127;
    const float4 sc = *reinterpret_cast<const float4*>(g_scale + c0);
    const float4 bi = *reinterpret_cast<const float4*>(g_bias + c0);
    v.x = fmaf(v.x, sc.x, bi.x); v.x = (v.x >= 0.0f) ? v.x : NEG_SLOPE * v.x;
    v.y = fmaf(v.y, sc.y, bi.y); v.y = (v.y >= 0.0f) ? v.y : NEG_SLOPE * v.y;
    v.z = fmaf(v.z, sc.z, bi.z); v.z = (v.z >= 0.0f) ? v.z : NEG_SLOPE * v.z;
    v.w = fmaf(v.w, sc.w, bi.w); v.w = (v.w >= 0.0f) ? v.w : NEG_SLOPE * v.w;
    reinterpret_cast<float4*>(x)[i] = v;
}

// =====================================================================
extern "C" void kernel_launch(void* const* d_in, const int* in_sizes, int n_in,
                              void* d_out, int out_size)
{
    const float* qp    = (const float*)d_in[0];
    const float* sp    = (const float*)d_in[1];
    const int*   nbr   = (const int*)  d_in[2];
    const float* feat  = (const float*)d_in[3];
    const float* kpts  = (const float*)d_in[4];
    const float* Wf    = (const float*)d_in[5];
    const float* gamma = (const float*)d_in[6];
    const float* beta  = (const float*)d_in[7];
    float* out = (float*)d_out;

    cudaFuncSetAttribute(k2_gemm_mma,
                         cudaFuncAttributeMaxDynamicSharedMemorySize, K2_SMEM);

    k0_prep<<<(RDIM * OUT_F + 255) / 256, 256>>>(Wf);
    k1_weighted<<<N_PTS / 4, 128>>>(qp, sp, nbr, feat, kpts);
    k2_gemm_mma<<<N_PTS / 128, 256, K2_SMEM>>>(out);
    k3b_finalize<<<OUT_F, 256>>>(gamma, beta);
    k4_bnrelu<<<(N_PTS * OUT_F / 4) / 256, 256>>>(out);
}